// round 6
// baseline (speedup 1.0000x reference)
#include <cuda_runtime.h>
#include <math.h>

#define H 128
#define W 128
#define B 8
#define NBLK 128
#define NTHR 512
#define G_EMPTY 40000            // > MAX_D2, fits u16: empty-row sentinel
#define MAX_D2 (127*127 + 127*127)

// Cross-block 1D row-distance table (u16) + per-CTA barrier flags.
__device__ unsigned short g_G[H * W];
__device__ unsigned g_flags[NBLK];

__global__ void __launch_bounds__(NTHR, 1)
edt_fused(const float* __restrict__ in, float* __restrict__ out) {
    const int tid = threadIdx.x;
    const int j   = tid & 127;   // column
    const int p   = tid >> 7;    // quarter 0..3
    const int row = blockIdx.x;  // phase 1: h ; phase 2: i

    __shared__ unsigned s_w[4];
    __shared__ int s_part[4][W];
    __shared__ float s_res[W];

    // ---------- Phase 1: mask ballot for this row (union over batch) ----------
    if (tid < 128) {
        bool m = false;
#pragma unroll
        for (int b = 0; b < B; b++)
            m |= in[b * (H * W) + row * W + j] > 0.5f;
        unsigned bal = __ballot_sync(0xFFFFFFFFu, m);
        if ((tid & 31) == 0) s_w[tid >> 5] = bal;
    }
    __syncthreads();

    // Nearest set bit left/right of column j, computed ONCE per (row, j).
    if (tid < 128) {
        unsigned long long lo = s_w[0] | ((unsigned long long)s_w[1] << 32);
        unsigned long long hi = s_w[2] | ((unsigned long long)s_w[3] << 32);
        int dr, dl;
        if (j < 64) {
            unsigned long long t = lo >> j;
            dr = t ? (__ffsll((long long)t) - 1)
                   : (hi ? (64 - j) + __ffsll((long long)hi) - 1 : 1024);
            unsigned long long u = lo << (63 - j);
            dl = u ? __clzll((long long)u) : 1024;
        } else {
            unsigned long long t = hi >> (j - 64);
            dr = t ? (__ffsll((long long)t) - 1) : 1024;
            unsigned long long u = hi << (127 - j);
            dl = u ? __clzll((long long)u)
                   : (lo ? (j - 63) + __clzll((long long)lo) : 1024);
        }
        int d = min(dl, dr);
        unsigned short gv = (d > 127) ? (unsigned short)G_EMPTY
                                      : (unsigned short)(d * d);
        __stcg(&g_G[row * W + j], gv);
    }

    // ---------- Grid barrier: single-writer flags, warp-parallel poll ----------
    __syncthreads();
    if (tid < 32) {
        unsigned gen = 0;
        if (tid == 0) {
            __threadfence();                       // release g_G stores
            gen = g_flags[row] + 1;                // single-writer: safe plain read
            asm volatile("st.volatile.global.u32 [%0], %1;"
                         :: "l"(g_flags + row), "r"(gen) : "memory");
        }
        gen = __shfl_sync(0xFFFFFFFFu, gen, 0);
        const unsigned* fp = g_flags + tid * 4;    // 32 lanes x 4 flags = 128
        for (;;) {
            unsigned a, b, c, d;
            asm volatile("ld.volatile.global.v4.u32 {%0,%1,%2,%3}, [%4];"
                         : "=r"(a), "=r"(b), "=r"(c), "=r"(d)
                         : "l"(fp) : "memory");
            bool done = (a >= gen) && (b >= gen) && (c >= gen) && (d >= gen);
            if (__ballot_sync(0xFFFFFFFFu, done) == 0xFFFFFFFFu) break;
        }
        __threadfence();                           // acquire before reading g_G
    }
    __syncthreads();

    // ---------- Phase 2: thread (j,p) scans h in [32p, 32p+32) ----------------
    {
        const int hbase = p << 5;
        int best = 0x7FFFFFFF;
#pragma unroll
        for (int k = 0; k < 32; k++) {
            int h  = hbase + k;
            int dh = row - h;
            int gv = (int)__ldcg(&g_G[h * W + j]);   // coalesced u16, MLP=32
            best = min(best, dh * dh + gv);
        }
        s_part[p][j] = best;
    }
    __syncthreads();

    // ---------- Reduce quarters, sqrt, broadcast to all 8 batches --------------
    if (tid < 128) {
        int b4 = min(min(s_part[0][j], s_part[1][j]),
                     min(s_part[2][j], s_part[3][j]));
        s_res[j] = (b4 > MAX_D2) ? INFINITY : sqrtf((float)b4);
    }
    __syncthreads();
    {
        float r = s_res[j];
        out[(2 * p)     * (H * W) + row * W + j] = r;
        out[(2 * p + 1) * (H * W) + row * W + j] = r;
    }
}

extern "C" void kernel_launch(void* const* d_in, const int* in_sizes, int n_in,
                              void* d_out, int out_size) {
    const float* in = (const float*)d_in[0];
    float* out = (float*)d_out;
    edt_fused<<<NBLK, NTHR>>>(in, out);
}

// round 7
// speedup vs baseline: 1.4337x; 1.4337x over previous
#include <cuda_runtime.h>
#include <math.h>

#define H 128
#define W 128
#define B 8
#define NBLK 32
#define RPB 4              // rows per block
#define NTHR 1024
#define G_EMPTY 40000      // > MAX_D2, fits u16: empty-row sentinel
#define MAX_D2 (127*127 + 127*127)

// Cross-block 1D row-distance table (u16) + barrier counter.
__device__ unsigned short g_G[H * W];
__device__ unsigned g_bar = 0;

__global__ void __launch_bounds__(NTHR, 1)
edt_fused(const float* __restrict__ in, float* __restrict__ out) {
    const int tid = threadIdx.x;
    const int j   = tid & 127;   // column 0..127
    const int q   = tid >> 7;    // slot 0..7
    const int rbase = blockIdx.x * RPB;

    __shared__ unsigned s_mw[RPB][4];
    __shared__ int s_part[RPB][8][W + 4];  // +4 pad: conflict-free qq-reduce

    // ---------- Phase 1: union mask for 4 rows (slots q<4, 8 LDGs each) ------
    if (q < RPB) {
        const int row = rbase + q;
        bool m = false;
#pragma unroll
        for (int b = 0; b < B; b++)
            m |= in[b * (H * W) + row * W + j] > 0.5f;
        unsigned bal = __ballot_sync(0xFFFFFFFFu, m);
        if ((j & 31) == 0) s_mw[q][j >> 5] = bal;
    }
    __syncthreads();

    // Nearest set bit left/right of column j, ONCE per (row, j); store u16 G.
    if (q < RPB) {
        const int row = rbase + q;
        unsigned long long lo = s_mw[q][0] | ((unsigned long long)s_mw[q][1] << 32);
        unsigned long long hi = s_mw[q][2] | ((unsigned long long)s_mw[q][3] << 32);
        int dr, dl;
        if (j < 64) {  // warp-uniform branch (warp spans 32 consecutive j)
            unsigned long long t = lo >> j;
            dr = t ? (__ffsll((long long)t) - 1)
                   : (hi ? (64 - j) + __ffsll((long long)hi) - 1 : 1024);
            unsigned long long u = lo << (63 - j);
            dl = u ? __clzll((long long)u) : 1024;
        } else {
            unsigned long long t = hi >> (j - 64);
            dr = t ? (__ffsll((long long)t) - 1) : 1024;
            unsigned long long u = hi << (127 - j);
            dl = u ? __clzll((long long)u)
                   : (lo ? (j - 63) + __clzll((long long)lo) : 1024);
        }
        int d = min(dl, dr);
        unsigned short gv = (d > 127) ? (unsigned short)G_EMPTY
                                      : (unsigned short)(d * d);
        __stcg(&g_G[row * W + j], gv);
    }

    // ---------- Grid barrier: 32 participants, single counter (R3-proven) ----
    __syncthreads();
    if (tid == 0) {
        __threadfence();                               // release g_G stores
        unsigned ticket = atomicAdd(&g_bar, 1u);
        unsigned target = (ticket / NBLK + 1u) * NBLK; // generation-safe replays
        volatile unsigned* vb = &g_bar;
        while (*vb < target) { }
        __threadfence();                               // acquire
    }
    __syncthreads();

    // ---------- Phase 2: slot q scans h in [16q,16q+16); reuse gv x4 rows ----
    {
        const int hbase = q << 4;
        int best0 = 0x7FFFFFFF, best1 = 0x7FFFFFFF;
        int best2 = 0x7FFFFFFF, best3 = 0x7FFFFFFF;
#pragma unroll
        for (int k = 0; k < 16; k++) {
            int h  = hbase + k;
            int gv = (int)__ldcg(&g_G[h * W + j]);     // coalesced u16, MLP=16
            int d0 = rbase + 0 - h;
            int d1 = rbase + 1 - h;
            int d2 = rbase + 2 - h;
            int d3 = rbase + 3 - h;
            best0 = min(best0, d0 * d0 + gv);
            best1 = min(best1, d1 * d1 + gv);
            best2 = min(best2, d2 * d2 + gv);
            best3 = min(best3, d3 * d3 + gv);
        }
        s_part[0][q][j] = best0;
        s_part[1][q][j] = best1;
        s_part[2][q][j] = best2;
        s_part[3][q][j] = best3;
    }
    __syncthreads();

    // ---------- Reduce 8 slots, sqrt, broadcast 8 batches (slots q<4) --------
    if (q < RPB) {
        int b4 = 0x7FFFFFFF;
#pragma unroll
        for (int qq = 0; qq < 8; qq++)
            b4 = min(b4, s_part[q][qq][j]);            // pad -> conflict-free
        float r = (b4 > MAX_D2) ? INFINITY : sqrtf((float)b4);
        const int row = rbase + q;
#pragma unroll
        for (int b = 0; b < B; b++)
            out[b * (H * W) + row * W + j] = r;
    }
}

extern "C" void kernel_launch(void* const* d_in, const int* in_sizes, int n_in,
                              void* d_out, int out_size) {
    const float* in = (const float*)d_in[0];
    float* out = (float*)d_out;
    edt_fused<<<NBLK, NTHR>>>(in, out);
}